// round 2
// baseline (speedup 1.0000x reference)
#include <cuda_runtime.h>
#include <cuda_fp16.h>

#define N_NODES 100000
#define N_EDGES 1600000
#define F0 69
#define F0P 72            // padded feature dims (36 half2)
#define F0H 36
#define F1 128
#define F2 64
#define F2H 32
#define NUM_GRAPHS 128
#define SCAN_NBLK ((N_NODES + 1023) / 1024)   // 98
#define NB1 16
#define NT1 (N_NODES / NB1)                   // 6250
#define NB2 32
#define NT2 (N_NODES / NB2)                   // 3125

// ---------------- scratch (static device globals; no runtime alloc) -------
__device__ int     g_deg_out[N_NODES];
__device__ int     g_deg_in[N_NODES];
__device__ float   g_inv_out[N_NODES];
__device__ float   g_inv_in[N_NODES];
__device__ int     g_row_ptr[N_NODES + 1];
__device__ int     g_cursor[N_NODES];
__device__ int     g_block_sums[128];
__device__ int     g_csr_src[N_EDGES];
__device__ __half2 g_x16[N_NODES * F0H];      // fp16 (x * inv_out), padded to 72 dims
__device__ float   g_agg1[N_NODES * F0P];     // normalized layer-1 aggregate (fp32)
__device__ float   g_h1n[N_NODES * F1];       // relu(agg1@W1) * inv_out
__device__ __half2 g_g2h[N_NODES * F2H];      // (h1n @ W2) as fp16
// --------------------------------------------------------------------------

__device__ __forceinline__ unsigned long long ffma2(unsigned long long a,
                                                    unsigned long long b,
                                                    unsigned long long c) {
    unsigned long long d;
    asm("fma.rn.f32x2 %0, %1, %2, %3;" : "=l"(d) : "l"(a), "l"(b), "l"(c));
    return d;
}

__global__ void k_init(float* __restrict__ out) {
    int i = blockIdx.x * blockDim.x + threadIdx.x;
    int stride = gridDim.x * blockDim.x;
    for (int j = i; j < N_NODES; j += stride) {
        g_deg_out[j] = 0;
        g_deg_in[j]  = 0;
        g_cursor[j]  = 0;
    }
    for (int j = i; j < NUM_GRAPHS * F2; j += stride) out[j] = 0.0f;
}

__global__ void k_deg(const int* __restrict__ src, const int* __restrict__ dst) {
    int e = blockIdx.x * blockDim.x + threadIdx.x;
    if (e < N_EDGES) {
        atomicAdd(&g_deg_out[src[e]], 1);
        atomicAdd(&g_deg_in[dst[e]], 1);
    }
}

// ---- 3-kernel exclusive scan of g_deg_in into g_row_ptr ------------------
__global__ void k_scan_local() {
    __shared__ int sh[1024];
    int t = threadIdx.x;
    int i = blockIdx.x * 1024 + t;
    int v = (i < N_NODES) ? g_deg_in[i] : 0;
    sh[t] = v;
    __syncthreads();
    for (int off = 1; off < 1024; off <<= 1) {
        int tmp = (t >= off) ? sh[t - off] : 0;
        __syncthreads();
        sh[t] += tmp;
        __syncthreads();
    }
    if (i < N_NODES) g_row_ptr[i] = sh[t] - v;
    if (t == 1023) g_block_sums[blockIdx.x] = sh[t];
}

__global__ void k_scan_partials() {
    __shared__ int sh[128];
    int t = threadIdx.x;
    int v = (t < SCAN_NBLK) ? g_block_sums[t] : 0;
    sh[t] = v;
    __syncthreads();
    for (int off = 1; off < 128; off <<= 1) {
        int tmp = (t >= off) ? sh[t - off] : 0;
        __syncthreads();
        sh[t] += tmp;
        __syncthreads();
    }
    if (t < SCAN_NBLK) g_block_sums[t] = sh[t] - v;
}

__global__ void k_scan_add() {   // also computes inv-sqrt degrees
    int i = blockIdx.x * 1024 + threadIdx.x;
    if (i < N_NODES) {
        g_row_ptr[i] += g_block_sums[i >> 10];
        g_inv_out[i] = rsqrtf(fmaxf((float)g_deg_out[i], 1.0f));
        g_inv_in[i]  = rsqrtf(fmaxf((float)g_deg_in[i], 1.0f));
    }
    if (i == 0) g_row_ptr[N_NODES] = N_EDGES;
}

__global__ void k_fill(const int* __restrict__ src, const int* __restrict__ dst) {
    int e = blockIdx.x * blockDim.x + threadIdx.x;
    if (e < N_EDGES) {
        int d = dst[e];
        int pos = g_row_ptr[d] + atomicAdd(&g_cursor[d], 1);
        g_csr_src[pos] = src[e];
    }
}

// ---- prepass: g_x16[i][d] = fp16(x[i][d] * inv_out[i]), pad to 72 --------
__global__ void k_prep(const float* __restrict__ x) {
    int idx = blockIdx.x * blockDim.x + threadIdx.x;
    if (idx >= N_NODES * F0H) return;
    int i = idx / F0H;
    int c = idx - i * F0H;
    int d = 2 * c;
    float w = g_inv_out[i];
    float v0 = (d < F0)     ? x[(size_t)i * F0 + d] * w     : 0.0f;
    float v1 = (d + 1 < F0) ? x[(size_t)i * F0 + d + 1] * w : 0.0f;
    g_x16[idx] = __floats2half2_rn(v0, v1);
}

// ---- SpMM layer 1: agg1[i] = inv_in[i] * sum_{e->i} x16[s] ---------------
__global__ void k_spmm1() {
    int i = blockIdx.x * 8 + (threadIdx.x >> 5);
    if (i >= N_NODES) return;
    int lane = threadIdx.x & 31;
    int beg = g_row_ptr[i], end = g_row_ptr[i + 1];
    bool hi = lane < 4;
    float2 a0 = make_float2(0.f, 0.f);
    float2 a1 = make_float2(0.f, 0.f);
    int e = beg;
    for (; e + 1 < end; e += 2) {
        int s0 = g_csr_src[e];
        int s1 = g_csr_src[e + 1];
        const __half2* p0 = g_x16 + (size_t)s0 * F0H;
        const __half2* p1 = g_x16 + (size_t)s1 * F0H;
        float2 u0 = __half22float2(p0[lane]);
        float2 u1 = __half22float2(p1[lane]);
        a0.x += u0.x + u1.x;
        a0.y += u0.y + u1.y;
        if (hi) {
            float2 w0 = __half22float2(p0[32 + lane]);
            float2 w1 = __half22float2(p1[32 + lane]);
            a1.x += w0.x + w1.x;
            a1.y += w0.y + w1.y;
        }
    }
    if (e < end) {
        const __half2* p0 = g_x16 + (size_t)g_csr_src[e] * F0H;
        float2 u0 = __half22float2(p0[lane]);
        a0.x += u0.x;
        a0.y += u0.y;
        if (hi) {
            float2 w0 = __half22float2(p0[32 + lane]);
            a1.x += w0.x;
            a1.y += w0.y;
        }
    }
    float sc = g_inv_in[i];
    float2* o = (float2*)(g_agg1 + (size_t)i * F0P);
    o[lane] = make_float2(a0.x * sc, a0.y * sc);
    if (hi) o[32 + lane] = make_float2(a1.x * sc, a1.y * sc);
}

// ---- GEMM1: h1n = relu(agg1 @ W1) * inv_out  (f32x2 packed) --------------
__global__ void __launch_bounds__(128) k_gemm1(const float* __restrict__ W1) {
    __shared__ float2 W1s2[F0 * 64];    // pair (col c, col c+64): 35328 B
    __shared__ float2 a_s2[NB1 * F0];   // duplicated (a,a): 8832 B
    int tid = threadIdx.x;
    for (int idx = tid; idx < F0 * 64; idx += 128) {
        int k = idx >> 6, c = idx & 63;
        W1s2[idx] = make_float2(W1[k * F1 + c], W1[k * F1 + c + 64]);
    }
    __syncthreads();
    int tj = tid & 31;
    int tn = tid >> 5;
    for (int tile = blockIdx.x; tile < NT1; tile += gridDim.x) {
        int i0 = tile * NB1;
        for (int idx = tid; idx < NB1 * F0; idx += 128) {
            int n = idx / F0, k = idx - n * F0;
            float v = g_agg1[(size_t)(i0 + n) * F0P + k];
            a_s2[idx] = make_float2(v, v);
        }
        __syncthreads();
        unsigned long long acc[4][2];
#pragma unroll
        for (int m = 0; m < 4; m++) { acc[m][0] = 0ull; acc[m][1] = 0ull; }
#pragma unroll 3
        for (int k = 0; k < F0; k++) {
            unsigned long long wA = *(const unsigned long long*)&W1s2[k * 64 + tj];
            unsigned long long wB = *(const unsigned long long*)&W1s2[k * 64 + tj + 32];
#pragma unroll
            for (int m = 0; m < 4; m++) {
                unsigned long long b = *(const unsigned long long*)&a_s2[(tn + 4 * m) * F0 + k];
                acc[m][0] = ffma2(b, wA, acc[m][0]);
                acc[m][1] = ffma2(b, wB, acc[m][1]);
            }
        }
#pragma unroll
        for (int m = 0; m < 4; m++) {
            int i = i0 + tn + 4 * m;
            float sc = g_inv_out[i];
            float2 p0 = *(float2*)&acc[m][0];
            float2 p1 = *(float2*)&acc[m][1];
            float* o = g_h1n + (size_t)i * F1;
            o[tj]      = fmaxf(p0.x, 0.f) * sc;
            o[tj + 64] = fmaxf(p0.y, 0.f) * sc;
            o[tj + 32] = fmaxf(p1.x, 0.f) * sc;
            o[tj + 96] = fmaxf(p1.y, 0.f) * sc;
        }
        __syncthreads();
    }
}

// ---- GEMM2: g2h = fp16(h1n @ W2)  (f32x2 packed, dynamic smem) -----------
__global__ void __launch_bounds__(128) k_gemm2(const float* __restrict__ W2) {
    extern __shared__ float2 dsm[];
    float2* W2s2 = dsm;                  // [F1*32] pair (2c, 2c+1): 32768 B
    float2* t_s2 = dsm + F1 * 32;        // [NB2*F1] duplicated: 32768 B
    int tid = threadIdx.x;
    const float2* W2v = (const float2*)W2;
    for (int idx = tid; idx < F1 * 32; idx += 128) W2s2[idx] = W2v[idx];
    __syncthreads();
    int tc = tid & 31;
    int tn = tid >> 5;
    for (int tile = blockIdx.x; tile < NT2; tile += gridDim.x) {
        int i0 = tile * NB2;
        for (int idx = tid; idx < NB2 * F1; idx += 128) {
            float v = g_h1n[(size_t)i0 * F1 + idx];
            t_s2[idx] = make_float2(v, v);
        }
        __syncthreads();
        unsigned long long acc[8];
#pragma unroll
        for (int m = 0; m < 8; m++) acc[m] = 0ull;
#pragma unroll 4
        for (int j = 0; j < F1; j++) {
            unsigned long long w = *(const unsigned long long*)&W2s2[j * 32 + tc];
#pragma unroll
            for (int m = 0; m < 8; m++) {
                unsigned long long b = *(const unsigned long long*)&t_s2[(tn + 4 * m) * F1 + j];
                acc[m] = ffma2(b, w, acc[m]);
            }
        }
#pragma unroll
        for (int m = 0; m < 8; m++) {
            int i = i0 + tn + 4 * m;
            float2 p = *(float2*)&acc[m];
            g_g2h[(size_t)i * F2H + tc] = __floats2half2_rn(p.x, p.y);
        }
        __syncthreads();
    }
}

// ---- SpMM layer 2 + relu + fused per-graph max readout -------------------
__global__ void k_spmm2(const int* __restrict__ graph_ids, float* __restrict__ out) {
    int i = blockIdx.x * 8 + (threadIdx.x >> 5);
    if (i >= N_NODES) return;
    int lane = threadIdx.x & 31;
    int beg = g_row_ptr[i], end = g_row_ptr[i + 1];
    float2 a = make_float2(0.f, 0.f);
    int e = beg;
    for (; e + 1 < end; e += 2) {
        int s0 = g_csr_src[e];
        int s1 = g_csr_src[e + 1];
        float2 u0 = __half22float2(g_g2h[(size_t)s0 * F2H + lane]);
        float2 u1 = __half22float2(g_g2h[(size_t)s1 * F2H + lane]);
        a.x += u0.x + u1.x;
        a.y += u0.y + u1.y;
    }
    if (e < end) {
        float2 u0 = __half22float2(g_g2h[(size_t)g_csr_src[e] * F2H + lane]);
        a.x += u0.x;
        a.y += u0.y;
    }
    float sc = g_inv_in[i];
    float v0 = fmaxf(a.x * sc, 0.0f);
    float v1 = fmaxf(a.y * sc, 0.0f);
    int g = graph_ids[i];
    int* ob = (int*)out + g * F2;
    // non-negative floats: int compare == float compare; out pre-zeroed
    atomicMax(ob + 2 * lane,     __float_as_int(v0));
    atomicMax(ob + 2 * lane + 1, __float_as_int(v1));
}

extern "C" void kernel_launch(void* const* d_in, const int* in_sizes, int n_in,
                              void* d_out, int out_size) {
    const float* x   = (const float*)d_in[0];
    const float* W1  = (const float*)d_in[1];
    const float* W2  = (const float*)d_in[2];
    const int*   src = (const int*)d_in[3];
    const int*   dst = (const int*)d_in[4];
    const int*   gid = (const int*)d_in[5];
    float* out = (float*)d_out;

    cudaFuncSetAttribute(k_gemm2, cudaFuncAttributeMaxDynamicSharedMemorySize, 65536);

    k_init<<<256, 256>>>(out);
    k_deg<<<(N_EDGES + 255) / 256, 256>>>(src, dst);
    k_scan_local<<<SCAN_NBLK, 1024>>>();
    k_scan_partials<<<1, 128>>>();
    k_scan_add<<<SCAN_NBLK, 1024>>>();
    k_prep<<<(N_NODES * F0H + 255) / 256, 256>>>(x);
    k_fill<<<(N_EDGES + 255) / 256, 256>>>(src, dst);
    k_spmm1<<<(N_NODES + 7) / 8, 256>>>();
    k_gemm1<<<740, 128>>>(W1);
    k_gemm2<<<444, 128, 65536>>>(W2);
    k_spmm2<<<(N_NODES + 7) / 8, 256>>>(gid, out);
}

// round 3
// speedup vs baseline: 1.0535x; 1.0535x over previous
#include <cuda_runtime.h>
#include <cuda_fp16.h>

#define N_NODES 100000
#define N_EDGES 1600000
#define F0 69
#define F0P 72            // padded feature dim (36 half2)
#define F0H 36
#define F1 128
#define F2 64
#define F2H 32
#define NUM_GRAPHS 128
#define SCAN_NBLK ((N_NODES + 1023) / 1024)   // 98
#define NB 16                                  // nodes per GEMM tile
#define N_TILES (N_NODES / NB)                 // 6250

// ---------------- scratch (static device globals; no runtime alloc) -------
__device__ int     g_deg_out[N_NODES];
__device__ int     g_deg_in[N_NODES];
__device__ float   g_inv_out[N_NODES];
__device__ float   g_inv_in[N_NODES];
__device__ int     g_row_ptr[N_NODES + 1];
__device__ int     g_cursor[N_NODES];
__device__ int     g_block_sums[128];
__device__ int     g_csr_src[N_EDGES];
__device__ __half2 g_x16[N_NODES * F0H];      // fp16 (x * inv_out), padded to 72
__device__ float   g_agg1[N_NODES * F0P];     // normalized layer-1 aggregate
__device__ float   g_h1n[N_NODES * F1];       // relu(agg1@W1) * inv_out
__device__ __half2 g_g2h[N_NODES * F2H];      // (h1n @ W2) as fp16
// --------------------------------------------------------------------------

__global__ void k_init(float* __restrict__ out) {
    int i = blockIdx.x * blockDim.x + threadIdx.x;
    int stride = gridDim.x * blockDim.x;
    for (int j = i; j < N_NODES; j += stride) {
        g_deg_out[j] = 0;
        g_deg_in[j]  = 0;
        g_cursor[j]  = 0;
    }
    for (int j = i; j < NUM_GRAPHS * F2; j += stride) out[j] = 0.0f;
}

__global__ void k_deg(const int* __restrict__ src, const int* __restrict__ dst) {
    int e = blockIdx.x * blockDim.x + threadIdx.x;
    if (e < N_EDGES) {
        atomicAdd(&g_deg_out[src[e]], 1);
        atomicAdd(&g_deg_in[dst[e]], 1);
    }
}

// ---- 3-kernel exclusive scan of g_deg_in into g_row_ptr ------------------
__global__ void k_scan_local() {
    __shared__ int sh[1024];
    int t = threadIdx.x;
    int i = blockIdx.x * 1024 + t;
    int v = (i < N_NODES) ? g_deg_in[i] : 0;
    sh[t] = v;
    __syncthreads();
    for (int off = 1; off < 1024; off <<= 1) {
        int tmp = (t >= off) ? sh[t - off] : 0;
        __syncthreads();
        sh[t] += tmp;
        __syncthreads();
    }
    if (i < N_NODES) g_row_ptr[i] = sh[t] - v;
    if (t == 1023) g_block_sums[blockIdx.x] = sh[t];
}

__global__ void k_scan_partials() {
    __shared__ int sh[128];
    int t = threadIdx.x;
    int v = (t < SCAN_NBLK) ? g_block_sums[t] : 0;
    sh[t] = v;
    __syncthreads();
    for (int off = 1; off < 128; off <<= 1) {
        int tmp = (t >= off) ? sh[t - off] : 0;
        __syncthreads();
        sh[t] += tmp;
        __syncthreads();
    }
    if (t < SCAN_NBLK) g_block_sums[t] = sh[t] - v;
}

__global__ void k_scan_add() {   // finalize row_ptr; compute inv-sqrt degrees
    int i = blockIdx.x * 1024 + threadIdx.x;
    if (i < N_NODES) {
        g_row_ptr[i] += g_block_sums[i >> 10];
        g_inv_out[i] = rsqrtf(fmaxf((float)g_deg_out[i], 1.0f));
        g_inv_in[i]  = rsqrtf(fmaxf((float)g_deg_in[i], 1.0f));
    }
    if (i == 0) g_row_ptr[N_NODES] = N_EDGES;
}

__global__ void k_fill(const int* __restrict__ src, const int* __restrict__ dst) {
    int e = blockIdx.x * blockDim.x + threadIdx.x;
    if (e < N_EDGES) {
        int d = dst[e];
        int pos = g_row_ptr[d] + atomicAdd(&g_cursor[d], 1);
        g_csr_src[pos] = src[e];
    }
}

// ---- prepass: g_x16[i][d] = fp16(x[i][d] * inv_out[i]), pad to 72 --------
__global__ void k_prep(const float* __restrict__ x) {
    int idx = blockIdx.x * blockDim.x + threadIdx.x;
    if (idx >= N_NODES * F0H) return;
    int i = idx / F0H;
    int c = idx - i * F0H;
    int d = 2 * c;
    float w = g_inv_out[i];
    float v0 = (d < F0)     ? x[(size_t)i * F0 + d] * w     : 0.0f;
    float v1 = (d + 1 < F0) ? x[(size_t)i * F0 + d + 1] * w : 0.0f;
    g_x16[idx] = __floats2half2_rn(v0, v1);
}

// ---- SpMM layer 1: agg1[i] = inv_in[i] * sum_{e->i} x16[s], unroll-4 -----
__global__ void k_spmm1() {
    int i = blockIdx.x * 8 + (threadIdx.x >> 5);
    if (i >= N_NODES) return;
    int lane = threadIdx.x & 31;
    int beg = g_row_ptr[i], end = g_row_ptr[i + 1];
    bool hi = lane < 4;
    float2 a0 = make_float2(0.f, 0.f);
    float2 a1 = make_float2(0.f, 0.f);
    int e = beg;
    for (; e + 3 < end; e += 4) {
        int s0 = g_csr_src[e],     s1 = g_csr_src[e + 1];
        int s2 = g_csr_src[e + 2], s3 = g_csr_src[e + 3];
        const __half2* p0 = g_x16 + (size_t)s0 * F0H;
        const __half2* p1 = g_x16 + (size_t)s1 * F0H;
        const __half2* p2 = g_x16 + (size_t)s2 * F0H;
        const __half2* p3 = g_x16 + (size_t)s3 * F0H;
        float2 u0 = __half22float2(p0[lane]);
        float2 u1 = __half22float2(p1[lane]);
        float2 u2 = __half22float2(p2[lane]);
        float2 u3 = __half22float2(p3[lane]);
        a0.x += (u0.x + u1.x) + (u2.x + u3.x);
        a0.y += (u0.y + u1.y) + (u2.y + u3.y);
        if (hi) {
            float2 w0 = __half22float2(p0[32 + lane]);
            float2 w1 = __half22float2(p1[32 + lane]);
            float2 w2 = __half22float2(p2[32 + lane]);
            float2 w3 = __half22float2(p3[32 + lane]);
            a1.x += (w0.x + w1.x) + (w2.x + w3.x);
            a1.y += (w0.y + w1.y) + (w2.y + w3.y);
        }
    }
    for (; e < end; e++) {
        const __half2* p0 = g_x16 + (size_t)g_csr_src[e] * F0H;
        float2 u0 = __half22float2(p0[lane]);
        a0.x += u0.x;
        a0.y += u0.y;
        if (hi) {
            float2 w0 = __half22float2(p0[32 + lane]);
            a1.x += w0.x;
            a1.y += w0.y;
        }
    }
    float sc = g_inv_in[i];
    float2* o = (float2*)(g_agg1 + (size_t)i * F0P);
    o[lane] = make_float2(a0.x * sc, a0.y * sc);
    if (hi) o[32 + lane] = make_float2(a1.x * sc, a1.y * sc);
}

// ---- GEMM1: h1n = relu(agg1 @ W1) * inv_out  (scalar, R1 form) -----------
__global__ void __launch_bounds__(128) k_gemm1(const float* __restrict__ W1) {
    __shared__ float W1s[F0 * F1];      // 35328 B
    __shared__ float a_s[NB * F0P];     // 4608 B
    int tid = threadIdx.x;
    for (int idx = tid; idx < F0 * F1; idx += 128) W1s[idx] = W1[idx];
    __syncthreads();
    int tj = tid & 31;
    int tn = tid >> 5;
    for (int tile = blockIdx.x; tile < N_TILES; tile += gridDim.x) {
        int i0 = tile * NB;
        {
            float2* asv = (float2*)a_s;
            const float2* gv = (const float2*)(g_agg1 + (size_t)i0 * F0P);
            for (int idx = tid; idx < NB * F0P / 2; idx += 128) asv[idx] = gv[idx];
        }
        __syncthreads();
        float acc[4][4];
#pragma unroll
        for (int m = 0; m < 4; m++)
#pragma unroll
            for (int mm = 0; mm < 4; mm++) acc[m][mm] = 0.f;
#pragma unroll 3
        for (int k = 0; k < F0; k++) {
            float w0 = W1s[k * F1 + tj];
            float w1 = W1s[k * F1 + tj + 32];
            float w2 = W1s[k * F1 + tj + 64];
            float w3 = W1s[k * F1 + tj + 96];
            float b0 = a_s[tn * F0P + k];
            float b1 = a_s[(tn + 4) * F0P + k];
            float b2 = a_s[(tn + 8) * F0P + k];
            float b3 = a_s[(tn + 12) * F0P + k];
            acc[0][0] += b0 * w0; acc[1][0] += b0 * w1; acc[2][0] += b0 * w2; acc[3][0] += b0 * w3;
            acc[0][1] += b1 * w0; acc[1][1] += b1 * w1; acc[2][1] += b1 * w2; acc[3][1] += b1 * w3;
            acc[0][2] += b2 * w0; acc[1][2] += b2 * w1; acc[2][2] += b2 * w2; acc[3][2] += b2 * w3;
            acc[0][3] += b3 * w0; acc[1][3] += b3 * w1; acc[2][3] += b3 * w2; acc[3][3] += b3 * w3;
        }
#pragma unroll
        for (int mm = 0; mm < 4; mm++) {
            int i = i0 + tn + 4 * mm;
            float sc = g_inv_out[i];
            float* o = g_h1n + (size_t)i * F1;
#pragma unroll
            for (int m = 0; m < 4; m++) {
                float v = acc[m][mm];
                v = v > 0.f ? v : 0.f;
                o[tj + 32 * m] = v * sc;
            }
        }
        __syncthreads();
    }
}

// ---- GEMM2: g2h = fp16(h1n @ W2)  (scalar; thread owns column pair) ------
__global__ void __launch_bounds__(128) k_gemm2(const float* __restrict__ W2) {
    __shared__ float2 W2s2[F1 * F2H];   // 32768 B: W2s2[j*32+c] = (W2[j][2c], W2[j][2c+1])
    __shared__ float t_s[NB * F1];      // 8192 B
    int tid = threadIdx.x;
    const float2* W2v = (const float2*)W2;
    for (int idx = tid; idx < F1 * F2H; idx += 128) W2s2[idx] = W2v[idx];
    __syncthreads();
    int tc = tid & 31;
    int tn = tid >> 5;
    for (int tile = blockIdx.x; tile < N_TILES; tile += gridDim.x) {
        int i0 = tile * NB;
        for (int idx = tid; idx < NB * F1; idx += 128)
            t_s[idx] = g_h1n[(size_t)i0 * F1 + idx];
        __syncthreads();
        float2 acc[4];
#pragma unroll
        for (int mm = 0; mm < 4; mm++) acc[mm] = make_float2(0.f, 0.f);
#pragma unroll 4
        for (int j = 0; j < F1; j++) {
            float2 w = W2s2[j * F2H + tc];
#pragma unroll
            for (int mm = 0; mm < 4; mm++) {
                float tv = t_s[(tn + 4 * mm) * F1 + j];
                acc[mm].x += tv * w.x;
                acc[mm].y += tv * w.y;
            }
        }
#pragma unroll
        for (int mm = 0; mm < 4; mm++) {
            int i = i0 + tn + 4 * mm;
            g_g2h[(size_t)i * F2H + tc] = __floats2half2_rn(acc[mm].x, acc[mm].y);
        }
        __syncthreads();
    }
}

// ---- SpMM layer 2 + relu + fused per-graph max readout, unroll-4 ---------
__global__ void k_spmm2(const int* __restrict__ graph_ids, float* __restrict__ out) {
    int i = blockIdx.x * 8 + (threadIdx.x >> 5);
    if (i >= N_NODES) return;
    int lane = threadIdx.x & 31;
    int beg = g_row_ptr[i], end = g_row_ptr[i + 1];
    float2 a = make_float2(0.f, 0.f);
    int e = beg;
    for (; e + 3 < end; e += 4) {
        int s0 = g_csr_src[e],     s1 = g_csr_src[e + 1];
        int s2 = g_csr_src[e + 2], s3 = g_csr_src[e + 3];
        float2 u0 = __half22float2(g_g2h[(size_t)s0 * F2H + lane]);
        float2 u1 = __half22float2(g_g2h[(size_t)s1 * F2H + lane]);
        float2 u2 = __half22float2(g_g2h[(size_t)s2 * F2H + lane]);
        float2 u3 = __half22float2(g_g2h[(size_t)s3 * F2H + lane]);
        a.x += (u0.x + u1.x) + (u2.x + u3.x);
        a.y += (u0.y + u1.y) + (u2.y + u3.y);
    }
    for (; e < end; e++) {
        float2 u0 = __half22float2(g_g2h[(size_t)g_csr_src[e] * F2H + lane]);
        a.x += u0.x;
        a.y += u0.y;
    }
    float sc = g_inv_in[i];
    float v0 = fmaxf(a.x * sc, 0.0f);
    float v1 = fmaxf(a.y * sc, 0.0f);
    int g = graph_ids[i];
    int* ob = (int*)out + g * F2;
    // non-negative floats: int compare == float compare; out pre-zeroed
    atomicMax(ob + 2 * lane,     __float_as_int(v0));
    atomicMax(ob + 2 * lane + 1, __float_as_int(v1));
}

extern "C" void kernel_launch(void* const* d_in, const int* in_sizes, int n_in,
                              void* d_out, int out_size) {
    const float* x   = (const float*)d_in[0];
    const float* W1  = (const float*)d_in[1];
    const float* W2  = (const float*)d_in[2];
    const int*   src = (const int*)d_in[3];
    const int*   dst = (const int*)d_in[4];
    const int*   gid = (const int*)d_in[5];
    float* out = (float*)d_out;

    k_init<<<256, 256>>>(out);
    k_deg<<<(N_EDGES + 255) / 256, 256>>>(src, dst);
    k_scan_local<<<SCAN_NBLK, 1024>>>();
    k_scan_partials<<<1, 128>>>();
    k_scan_add<<<SCAN_NBLK, 1024>>>();
    k_prep<<<(N_NODES * F0H + 255) / 256, 256>>>(x);
    k_fill<<<(N_EDGES + 255) / 256, 256>>>(src, dst);
    k_spmm1<<<(N_NODES + 7) / 8, 256>>>();
    k_gemm1<<<740, 128>>>(W1);
    k_gemm2<<<740, 128>>>(W2);
    k_spmm2<<<(N_NODES + 7) / 8, 256>>>(gid, out);
}

// round 4
// speedup vs baseline: 1.0866x; 1.0314x over previous
#include <cuda_runtime.h>
#include <cuda_fp16.h>
#include <cstdint>

#define N_NODES 100000
#define NPAD    100032            // 64*1563, padded row count for GEMM tiles
#define N_EDGES 1600000
#define F0 69
#define F0P 72                    // padded K for layer 1 (9 tf32 k-steps)
#define F1 128
#define F2 64
#define NUM_GRAPHS 128
#define SCAN_NBLK ((N_NODES + 1023) / 1024)   // 98
#define MT 64                     // M rows per GEMM CTA tile
#define N_TILES (NPAD / MT)       // 1563

// ---------------- scratch (static device globals; no runtime alloc) -------
__device__ int   g_deg_out[N_NODES];
__device__ int   g_deg_in[N_NODES];
__device__ float g_inv_out[NPAD];            // pad rows stay 0 (never written)
__device__ float g_inv_in[N_NODES];
__device__ int   g_row_ptr[N_NODES + 1];
__device__ int   g_cursor[N_NODES];
__device__ int   g_block_sums[128];
__device__ int   g_csr_src[N_EDGES];
__device__ float g_xn[N_NODES * F0P];        // x * inv_out, padded+aligned rows
__device__ float g_agg1[NPAD * F0P];         // tf32-rounded; pad rows stay 0
__device__ float g_h1n[NPAD * F1];           // tf32-rounded relu(agg@W1)*inv_out
__device__ float g_g2[NPAD * F2];            // h1n @ W2
// --------------------------------------------------------------------------

__device__ __forceinline__ unsigned tf32u(float f) {
    unsigned u;
    asm("cvt.rna.tf32.f32 %0, %1;" : "=r"(u) : "f"(f));
    return u;
}

__device__ __forceinline__ void mma_tf32(float d[4], const unsigned a[4], const unsigned b[2]) {
    asm volatile(
        "mma.sync.aligned.m16n8k8.row.col.f32.tf32.tf32.f32 "
        "{%0,%1,%2,%3}, {%4,%5,%6,%7}, {%8,%9}, {%0,%1,%2,%3};"
        : "+f"(d[0]), "+f"(d[1]), "+f"(d[2]), "+f"(d[3])
        : "r"(a[0]), "r"(a[1]), "r"(a[2]), "r"(a[3]), "r"(b[0]), "r"(b[1]));
}

__global__ void k_init(float* __restrict__ out) {
    int i = blockIdx.x * blockDim.x + threadIdx.x;
    int stride = gridDim.x * blockDim.x;
    for (int j = i; j < N_NODES; j += stride) {
        g_deg_out[j] = 0;
        g_deg_in[j]  = 0;
        g_cursor[j]  = 0;
    }
    for (int j = i; j < NUM_GRAPHS * F2; j += stride) out[j] = 0.0f;
}

__global__ void k_deg(const int* __restrict__ src, const int* __restrict__ dst) {
    int e = blockIdx.x * blockDim.x + threadIdx.x;
    if (e < N_EDGES) {
        atomicAdd(&g_deg_out[src[e]], 1);
        atomicAdd(&g_deg_in[dst[e]], 1);
    }
}

// ---- 3-kernel exclusive scan of g_deg_in into g_row_ptr ------------------
__global__ void k_scan_local() {
    __shared__ int sh[1024];
    int t = threadIdx.x;
    int i = blockIdx.x * 1024 + t;
    int v = (i < N_NODES) ? g_deg_in[i] : 0;
    sh[t] = v;
    __syncthreads();
    for (int off = 1; off < 1024; off <<= 1) {
        int tmp = (t >= off) ? sh[t - off] : 0;
        __syncthreads();
        sh[t] += tmp;
        __syncthreads();
    }
    if (i < N_NODES) g_row_ptr[i] = sh[t] - v;
    if (t == 1023) g_block_sums[blockIdx.x] = sh[t];
}

__global__ void k_scan_partials() {
    __shared__ int sh[128];
    int t = threadIdx.x;
    int v = (t < SCAN_NBLK) ? g_block_sums[t] : 0;
    sh[t] = v;
    __syncthreads();
    for (int off = 1; off < 128; off <<= 1) {
        int tmp = (t >= off) ? sh[t - off] : 0;
        __syncthreads();
        sh[t] += tmp;
        __syncthreads();
    }
    if (t < SCAN_NBLK) g_block_sums[t] = sh[t] - v;
}

__global__ void k_scan_add() {   // finalize row_ptr; compute inv-sqrt degrees
    int i = blockIdx.x * 1024 + threadIdx.x;
    if (i < N_NODES) {
        g_row_ptr[i] += g_block_sums[i >> 10];
        g_inv_out[i] = rsqrtf(fmaxf((float)g_deg_out[i], 1.0f));
        g_inv_in[i]  = rsqrtf(fmaxf((float)g_deg_in[i], 1.0f));
    }
    if (i == 0) g_row_ptr[N_NODES] = N_EDGES;
}

__global__ void k_fill(const int* __restrict__ src, const int* __restrict__ dst) {
    int e = blockIdx.x * blockDim.x + threadIdx.x;
    if (e < N_EDGES) {
        int d = dst[e];
        int pos = g_row_ptr[d] + atomicAdd(&g_cursor[d], 1);
        g_csr_src[pos] = src[e];
    }
}

// ---- prepass: g_xn[i][d] = x[i][d] * inv_out[i], padded to 72, aligned ---
__global__ void k_prep(const float* __restrict__ x) {
    int idx = blockIdx.x * blockDim.x + threadIdx.x;
    if (idx >= N_NODES * F0P) return;
    int i = idx / F0P;
    int d = idx - i * F0P;
    float w = g_inv_out[i];
    g_xn[idx] = (d < F0) ? x[(size_t)i * F0 + d] * w : 0.0f;
}

// ---- SpMM layer 1: agg1[i] = tf32(inv_in[i] * sum_{e->i} xn[s]) ----------
__global__ void k_spmm1() {
    int i = blockIdx.x * 8 + (threadIdx.x >> 5);
    if (i >= N_NODES) return;
    int lane = threadIdx.x & 31;
    int beg = g_row_ptr[i], end = g_row_ptr[i + 1];
    bool hi = lane < 4;
    const float2* base = (const float2*)g_xn;   // row stride 36 float2
    float2 a0 = make_float2(0.f, 0.f);
    float2 a1 = make_float2(0.f, 0.f);
    int e = beg;
    for (; e + 3 < end; e += 4) {
        const float2* p0 = base + (size_t)g_csr_src[e]     * 36;
        const float2* p1 = base + (size_t)g_csr_src[e + 1] * 36;
        const float2* p2 = base + (size_t)g_csr_src[e + 2] * 36;
        const float2* p3 = base + (size_t)g_csr_src[e + 3] * 36;
        float2 u0 = p0[lane], u1 = p1[lane], u2 = p2[lane], u3 = p3[lane];
        a0.x += (u0.x + u1.x) + (u2.x + u3.x);
        a0.y += (u0.y + u1.y) + (u2.y + u3.y);
        if (hi) {
            float2 w0 = p0[32 + lane], w1 = p1[32 + lane];
            float2 w2 = p2[32 + lane], w3 = p3[32 + lane];
            a1.x += (w0.x + w1.x) + (w2.x + w3.x);
            a1.y += (w0.y + w1.y) + (w2.y + w3.y);
        }
    }
    for (; e < end; e++) {
        const float2* p0 = base + (size_t)g_csr_src[e] * 36;
        float2 u0 = p0[lane];
        a0.x += u0.x;
        a0.y += u0.y;
        if (hi) {
            float2 w0 = p0[32 + lane];
            a1.x += w0.x;
            a1.y += w0.y;
        }
    }
    float sc = g_inv_in[i];
    float2* o = (float2*)(g_agg1 + (size_t)i * F0P);
    o[lane] = make_float2(__uint_as_float(tf32u(a0.x * sc)),
                          __uint_as_float(tf32u(a0.y * sc)));
    if (hi)
        o[32 + lane] = make_float2(__uint_as_float(tf32u(a1.x * sc)),
                                   __uint_as_float(tf32u(a1.y * sc)));
}

// ---- GEMM1 (tensor cores): h1n = tf32(relu(agg1 @ W1) * inv_out) ---------
// CTA: 256 thr = 8 warps (4 m x 2 n). Tile M=64, N=128, K=72 (9 k-steps).
__global__ void __launch_bounds__(256) k_gemm1(const float* __restrict__ W1) {
    extern __shared__ float sm1[];
    float* Bs = sm1;              // [128][72]  (n-major)  36864 B
    float* As = sm1 + F1 * F0P;   // [64][72]              18432 B
    int tid = threadIdx.x;
    for (int idx = tid; idx < F1 * F0P; idx += 256) {
        int n = idx / F0P, k = idx - n * F0P;
        float v = (k < F0) ? W1[k * F1 + n] : 0.0f;
        Bs[idx] = __uint_as_float(tf32u(v));
    }
    int warp = tid >> 5, lane = tid & 31;
    int wm = warp & 3, wn = warp >> 2;
    int g = lane >> 2, tg = lane & 3;
    const unsigned* Asu = (const unsigned*)As;
    const unsigned* Bsu = (const unsigned*)Bs;
    for (int tile = blockIdx.x; tile < N_TILES; tile += gridDim.x) {
        int i0 = tile * MT;
        __syncthreads();
        {
            const float4* src4 = (const float4*)(g_agg1 + (size_t)i0 * F0P);
            float4* dst4 = (float4*)As;
            for (int idx = tid; idx < MT * F0P / 4; idx += 256) dst4[idx] = src4[idx];
        }
        __syncthreads();
        float d[8][4];
#pragma unroll
        for (int nf = 0; nf < 8; nf++)
#pragma unroll
            for (int q = 0; q < 4; q++) d[nf][q] = 0.f;
        int ar = wm * 16 + g;
#pragma unroll
        for (int ks = 0; ks < 9; ks++) {
            int k0 = ks * 8;
            unsigned a[4];
            a[0] = Asu[ar * F0P + k0 + tg];
            a[1] = Asu[(ar + 8) * F0P + k0 + tg];
            a[2] = Asu[ar * F0P + k0 + tg + 4];
            a[3] = Asu[(ar + 8) * F0P + k0 + tg + 4];
#pragma unroll
            for (int nf = 0; nf < 8; nf++) {
                int bc = wn * 64 + nf * 8 + g;
                unsigned b[2];
                b[0] = Bsu[bc * F0P + k0 + tg];
                b[1] = Bsu[bc * F0P + k0 + tg + 4];
                mma_tf32(d[nf], a, b);
            }
        }
        int r0 = i0 + wm * 16 + g;
        float s0 = g_inv_out[r0];
        float s1 = g_inv_out[r0 + 8];
#pragma unroll
        for (int nf = 0; nf < 8; nf++) {
            int c = wn * 64 + nf * 8 + tg * 2;
            float2 v0, v1;
            v0.x = __uint_as_float(tf32u(fmaxf(d[nf][0], 0.f) * s0));
            v0.y = __uint_as_float(tf32u(fmaxf(d[nf][1], 0.f) * s0));
            v1.x = __uint_as_float(tf32u(fmaxf(d[nf][2], 0.f) * s1));
            v1.y = __uint_as_float(tf32u(fmaxf(d[nf][3], 0.f) * s1));
            *(float2*)(g_h1n + (size_t)r0 * F1 + c) = v0;
            *(float2*)(g_h1n + (size_t)(r0 + 8) * F1 + c) = v1;
        }
    }
}

// ---- GEMM2 (tensor cores): g2 = h1n @ W2 ---------------------------------
// CTA: 256 thr = 8 warps (4 m x 2 n). Tile M=64, N=64, K=128 (16 k-steps).
#define LDK 132
__global__ void __launch_bounds__(256) k_gemm2(const float* __restrict__ W2) {
    extern __shared__ float sm2[];
    float* Bs = sm2;              // [64][132]  33792 B
    float* As = sm2 + F2 * LDK;   // [64][132]  33792 B
    int tid = threadIdx.x;
    for (int idx = tid; idx < F2 * LDK; idx += 256) {
        int n = idx / LDK, k = idx - n * LDK;
        float v = (k < F1) ? W2[k * F2 + n] : 0.0f;
        Bs[idx] = __uint_as_float(tf32u(v));
    }
    int warp = tid >> 5, lane = tid & 31;
    int wm = warp & 3, wn = warp >> 2;
    int g = lane >> 2, tg = lane & 3;
    const unsigned* Asu = (const unsigned*)As;
    const unsigned* Bsu = (const unsigned*)Bs;
    for (int tile = blockIdx.x; tile < N_TILES; tile += gridDim.x) {
        int i0 = tile * MT;
        __syncthreads();
        {
            const float4* src4 = (const float4*)(g_h1n + (size_t)i0 * F1);
            for (int idx = tid; idx < MT * F1 / 4; idx += 256) {
                int row = idx >> 5, c4 = idx & 31;
                *(float4*)(As + row * LDK + c4 * 4) = src4[idx];
            }
        }
        __syncthreads();
        float d[4][4];
#pragma unroll
        for (int nf = 0; nf < 4; nf++)
#pragma unroll
            for (int q = 0; q < 4; q++) d[nf][q] = 0.f;
        int ar = wm * 16 + g;
#pragma unroll
        for (int ks = 0; ks < 16; ks++) {
            int k0 = ks * 8;
            unsigned a[4];
            a[0] = Asu[ar * LDK + k0 + tg];
            a[1] = Asu[(ar + 8) * LDK + k0 + tg];
            a[2] = Asu[ar * LDK + k0 + tg + 4];
            a[3] = Asu[(ar + 8) * LDK + k0 + tg + 4];
#pragma unroll
            for (int nf = 0; nf < 4; nf++) {
                int bc = wn * 32 + nf * 8 + g;
                unsigned b[2];
                b[0] = Bsu[bc * LDK + k0 + tg];
                b[1] = Bsu[bc * LDK + k0 + tg + 4];
                mma_tf32(d[nf], a, b);
            }
        }
        int r0 = i0 + wm * 16 + g;
#pragma unroll
        for (int nf = 0; nf < 4; nf++) {
            int c = wn * 32 + nf * 8 + tg * 2;
            *(float2*)(g_g2 + (size_t)r0 * F2 + c)       = make_float2(d[nf][0], d[nf][1]);
            *(float2*)(g_g2 + (size_t)(r0 + 8) * F2 + c) = make_float2(d[nf][2], d[nf][3]);
        }
    }
}

// ---- SpMM layer 2 + relu + fused per-graph max readout, unroll-4 ---------
__global__ void k_spmm2(const int* __restrict__ graph_ids, float* __restrict__ out) {
    int i = blockIdx.x * 8 + (threadIdx.x >> 5);
    if (i >= N_NODES) return;
    int lane = threadIdx.x & 31;
    int beg = g_row_ptr[i], end = g_row_ptr[i + 1];
    const float2* base = (const float2*)g_g2;   // row stride 32 float2
    float2 a = make_float2(0.f, 0.f);
    int e = beg;
    for (; e + 3 < end; e += 4) {
        float2 u0 = base[(size_t)g_csr_src[e]     * 32 + lane];
        float2 u1 = base[(size_t)g_csr_src[e + 1] * 32 + lane];
        float2 u2 = base[(size_t)g_csr_src[e + 2] * 32 + lane];
        float2 u3 = base[(size_t)g_csr_src[e + 3] * 32 + lane];
        a.x += (u0.x + u1.x) + (u2.x + u3.x);
        a.y += (u0.y + u1.y) + (u2.y + u3.y);
    }
    for (; e < end; e++) {
        float2 u0 = base[(size_t)g_csr_src[e] * 32 + lane];
        a.x += u0.x;
        a.y += u0.y;
    }
    float sc = g_inv_in[i];
    float v0 = fmaxf(a.x * sc, 0.0f);
    float v1 = fmaxf(a.y * sc, 0.0f);
    int g = graph_ids[i];
    int* ob = (int*)out + g * F2;
    // non-negative floats: int compare == float compare; out pre-zeroed
    atomicMax(ob + 2 * lane,     __float_as_int(v0));
    atomicMax(ob + 2 * lane + 1, __float_as_int(v1));
}

extern "C" void kernel_launch(void* const* d_in, const int* in_sizes, int n_in,
                              void* d_out, int out_size) {
    const float* x   = (const float*)d_in[0];
    const float* W1  = (const float*)d_in[1];
    const float* W2  = (const float*)d_in[2];
    const int*   src = (const int*)d_in[3];
    const int*   dst = (const int*)d_in[4];
    const int*   gid = (const int*)d_in[5];
    float* out = (float*)d_out;

    static int smem_set = 0;
    if (!smem_set) {
        cudaFuncSetAttribute(k_gemm1, cudaFuncAttributeMaxDynamicSharedMemorySize, 56320);
        cudaFuncSetAttribute(k_gemm2, cudaFuncAttributeMaxDynamicSharedMemorySize, 68608);
        smem_set = 1;
    }

    k_init<<<256, 256>>>(out);
    k_deg<<<(N_EDGES + 255) / 256, 256>>>(src, dst);
    k_scan_local<<<SCAN_NBLK, 1024>>>();
    k_scan_partials<<<1, 128>>>();
    k_scan_add<<<SCAN_NBLK, 1024>>>();
    k_prep<<<(N_NODES * F0P + 255) / 256, 256>>>(x);
    k_fill<<<(N_EDGES + 255) / 256, 256>>>(src, dst);
    k_spmm1<<<(N_NODES + 7) / 8, 256>>>();
    k_gemm1<<<444, 256, (F1 * F0P + MT * F0P) * 4>>>(W1);
    k_gemm2<<<444, 256, (F2 * LDK + MT * LDK) * 4>>>(W2);
    k_spmm2<<<(N_NODES + 7) / 8, 256>>>(gid, out);
}

// round 5
// speedup vs baseline: 1.1792x; 1.0852x over previous
#include <cuda_runtime.h>
#include <cstdint>

#define N_NODES 100000
#define NPAD2   100096            // 128*782, padded rows for fused GEMM tiles
#define N_EDGES 1600000
#define F0 69
#define F0P 72                    // padded K for layer 1 (9 tf32 k-steps)
#define F1 128
#define F2 64
#define NUM_GRAPHS 128
#define SCAN_NBLK ((N_NODES + 1023) / 1024)   // 98
#define MT2 128                   // M rows per fused GEMM tile
#define N_TILES2 (NPAD2 / MT2)    // 782
#define LDA1 76                   // As stride  (conflict-free for tf32 frags)
#define LDB1 76                   // W1s stride
#define LDH  132                  // Hs / W2s stride
// smem bytes for fused gemm
#define SM_W1 (F1 * LDB1 * 4)       // 38912
#define SM_W2 (F2 * LDH * 4)        // 33792
#define SM_A  (MT2 * LDA1 * 4)      // 38912
#define SM_H  (MT2 * LDH * 4)       // 67584
#define SM_TOTAL (SM_W1 + SM_W2 + SM_A + SM_H)   // 179200

// ---------------- scratch (static device globals; no runtime alloc) -------
__device__ int   g_deg_out[N_NODES];
__device__ int   g_deg_in[N_NODES];
__device__ float g_inv_out[NPAD2];           // pad rows stay 0 (zero-init, never written)
__device__ float g_inv_in[N_NODES];
__device__ int   g_row_ptr[N_NODES + 1];
__device__ int   g_cursor[N_NODES];
__device__ int   g_block_sums[128];
__device__ int   g_csr_src[N_EDGES];
__device__ float g_agg1[NPAD2 * F0P];        // tf32-rounded; pad rows/cols stay 0
__device__ float g_g2[NPAD2 * F2];           // fused-gemm output
// --------------------------------------------------------------------------

__device__ __forceinline__ unsigned tf32u(float f) {
    unsigned u;
    asm("cvt.rna.tf32.f32 %0, %1;" : "=r"(u) : "f"(f));
    return u;
}
__device__ __forceinline__ float tf32f(float f) { return __uint_as_float(tf32u(f)); }

__device__ __forceinline__ void mma_tf32(float d[4], const unsigned a[4], const unsigned b[2]) {
    asm volatile(
        "mma.sync.aligned.m16n8k8.row.col.f32.tf32.tf32.f32 "
        "{%0,%1,%2,%3}, {%4,%5,%6,%7}, {%8,%9}, {%0,%1,%2,%3};"
        : "+f"(d[0]), "+f"(d[1]), "+f"(d[2]), "+f"(d[3])
        : "r"(a[0]), "r"(a[1]), "r"(a[2]), "r"(a[3]), "r"(b[0]), "r"(b[1]));
}

__global__ void k_init(float* __restrict__ out) {
    int i = blockIdx.x * blockDim.x + threadIdx.x;
    int stride = gridDim.x * blockDim.x;
    for (int j = i; j < N_NODES; j += stride) {
        g_deg_out[j] = 0;
        g_deg_in[j]  = 0;
    }
    for (int j = i; j < NUM_GRAPHS * F2; j += stride) out[j] = 0.0f;
}

__global__ void k_deg(const int* __restrict__ src, const int* __restrict__ dst) {
    int e = blockIdx.x * blockDim.x + threadIdx.x;
    if (e < N_EDGES) {
        atomicAdd(&g_deg_out[src[e]], 1);
        atomicAdd(&g_deg_in[dst[e]], 1);
    }
}

// ---- 3-kernel exclusive scan of g_deg_in into g_row_ptr ------------------
__global__ void k_scan_local() {
    __shared__ int sh[1024];
    int t = threadIdx.x;
    int i = blockIdx.x * 1024 + t;
    int v = (i < N_NODES) ? g_deg_in[i] : 0;
    sh[t] = v;
    __syncthreads();
    for (int off = 1; off < 1024; off <<= 1) {
        int tmp = (t >= off) ? sh[t - off] : 0;
        __syncthreads();
        sh[t] += tmp;
        __syncthreads();
    }
    if (i < N_NODES) g_row_ptr[i] = sh[t] - v;
    if (t == 1023) g_block_sums[blockIdx.x] = sh[t];
}

__global__ void k_scan_partials() {
    __shared__ int sh[128];
    int t = threadIdx.x;
    int v = (t < SCAN_NBLK) ? g_block_sums[t] : 0;
    sh[t] = v;
    __syncthreads();
    for (int off = 1; off < 128; off <<= 1) {
        int tmp = (t >= off) ? sh[t - off] : 0;
        __syncthreads();
        sh[t] += tmp;
        __syncthreads();
    }
    if (t < SCAN_NBLK) g_block_sums[t] = sh[t] - v;
}

__global__ void k_scan_add() {   // finalize row_ptr; prime fill cursor; inv-sqrt degs
    int i = blockIdx.x * 1024 + threadIdx.x;
    if (i < N_NODES) {
        int rp = g_row_ptr[i] + g_block_sums[i >> 10];
        g_row_ptr[i] = rp;
        g_cursor[i]  = rp;        // fill uses cursor directly
        g_inv_out[i] = rsqrtf(fmaxf((float)g_deg_out[i], 1.0f));
        g_inv_in[i]  = rsqrtf(fmaxf((float)g_deg_in[i], 1.0f));
    }
    if (i == 0) g_row_ptr[N_NODES] = N_EDGES;
}

__global__ void k_fill(const int* __restrict__ src, const int* __restrict__ dst) {
    int e = blockIdx.x * blockDim.x + threadIdx.x;
    if (e < N_EDGES) {
        int pos = atomicAdd(&g_cursor[dst[e]], 1);
        g_csr_src[pos] = src[e];
    }
}

// ---- SpMM layer 1 (R1-style direct x gather) + tf32 epilogue -------------
__global__ void k_spmm1(const float* __restrict__ x) {
    int i = blockIdx.x * 8 + (threadIdx.x >> 5);
    if (i >= N_NODES) return;
    int lane = threadIdx.x & 31;
    int beg = g_row_ptr[i], end = g_row_ptr[i + 1];
    float a0 = 0.f, a1 = 0.f, a2 = 0.f;
    int e = beg;
    for (; e + 1 < end; e += 2) {
        int s0 = g_csr_src[e];
        int s1 = g_csr_src[e + 1];
        float w0 = g_inv_out[s0];
        float w1 = g_inv_out[s1];
        const float* p0 = x + (size_t)s0 * F0;
        const float* p1 = x + (size_t)s1 * F0;
        a0 += p0[lane] * w0 + p1[lane] * w1;
        a1 += p0[lane + 32] * w0 + p1[lane + 32] * w1;
        if (lane < F0 - 64) a2 += p0[lane + 64] * w0 + p1[lane + 64] * w1;
    }
    if (e < end) {
        int s0 = g_csr_src[e];
        float w0 = g_inv_out[s0];
        const float* p0 = x + (size_t)s0 * F0;
        a0 += p0[lane] * w0;
        a1 += p0[lane + 32] * w0;
        if (lane < F0 - 64) a2 += p0[lane + 64] * w0;
    }
    float sc = g_inv_in[i];
    float* o = g_agg1 + (size_t)i * F0P;
    o[lane]      = tf32f(a0 * sc);
    o[lane + 32] = tf32f(a1 * sc);
    if (lane < F0 - 64) o[lane + 64] = tf32f(a2 * sc);
}

// ---- Fused GEMM1+GEMM2 (tensor cores, h1n never leaves smem) -------------
// 512 thr = 16 warps (4m x 4n). Tile M=128. MMA1: 128x128x72. MMA2: 128x64x128.
__global__ void __launch_bounds__(512, 1) k_gemm12(const float* __restrict__ W1,
                                                   const float* __restrict__ W2) {
    extern __shared__ float sm[];
    float* W1s = sm;                               // [128 n][76]
    float* W2s = sm + F1 * LDB1;                   // [64 n][132]
    float* As  = W2s + F2 * LDH;                   // [128 m][76]
    float* Hs  = As + MT2 * LDA1;                  // [128 m][132]
    int tid = threadIdx.x;
    // load + round weights once
    for (int idx = tid; idx < F1 * F0P; idx += 512) {
        int n = idx / F0P, k = idx - n * F0P;
        W1s[n * LDB1 + k] = (k < F0) ? tf32f(W1[k * F1 + n]) : 0.0f;
    }
    for (int idx = tid; idx < F2 * F1; idx += 512) {
        int n = idx >> 7, k = idx & 127;
        W2s[n * LDH + k] = tf32f(W2[k * F2 + n]);
    }
    int warp = tid >> 5, lane = tid & 31;
    int wm = warp & 3, wn = warp >> 2;
    int g = lane >> 2, tg = lane & 3;
    const unsigned* W1u = (const unsigned*)W1s;
    const unsigned* W2u = (const unsigned*)W2s;
    const unsigned* Asu = (const unsigned*)As;
    const unsigned* Hsu = (const unsigned*)Hs;
    int m0 = wm * 32;

    for (int tile = blockIdx.x; tile < N_TILES2; tile += gridDim.x) {
        int i0 = tile * MT2;
        __syncthreads();   // prior tile fully consumed As/Hs (and covers W load on iter 0)
        // stage A tile [128][72] -> stride 76
        for (int idx = tid; idx < MT2 * 18; idx += 512) {
            int row = idx / 18, q = idx - row * 18;
            float4 v = *(const float4*)(g_agg1 + (size_t)(i0 + row) * F0P + q * 4);
            *(float4*)(As + row * LDA1 + q * 4) = v;
        }
        __syncthreads();
        // ---- MMA1: H = relu(A @ W1) * inv_out, tf32-rounded into Hs ----
        {
            float d[2][4][4];
#pragma unroll
            for (int mf = 0; mf < 2; mf++)
#pragma unroll
                for (int nf = 0; nf < 4; nf++)
#pragma unroll
                    for (int q = 0; q < 4; q++) d[mf][nf][q] = 0.f;
#pragma unroll
            for (int ks = 0; ks < 9; ks++) {
                int k0 = ks * 8;
                unsigned a[2][4];
#pragma unroll
                for (int mf = 0; mf < 2; mf++) {
                    int ar = m0 + mf * 16 + g;
                    a[mf][0] = Asu[ar * LDA1 + k0 + tg];
                    a[mf][1] = Asu[(ar + 8) * LDA1 + k0 + tg];
                    a[mf][2] = Asu[ar * LDA1 + k0 + tg + 4];
                    a[mf][3] = Asu[(ar + 8) * LDA1 + k0 + tg + 4];
                }
#pragma unroll
                for (int nf = 0; nf < 4; nf++) {
                    int bc = wn * 32 + nf * 8 + g;
                    unsigned b[2];
                    b[0] = W1u[bc * LDB1 + k0 + tg];
                    b[1] = W1u[bc * LDB1 + k0 + tg + 4];
                    mma_tf32(d[0][nf], a[0], b);
                    mma_tf32(d[1][nf], a[1], b);
                }
            }
#pragma unroll
            for (int mf = 0; mf < 2; mf++) {
                int r0 = m0 + mf * 16 + g;
                float s0 = g_inv_out[i0 + r0];
                float s1 = g_inv_out[i0 + r0 + 8];
#pragma unroll
                for (int nf = 0; nf < 4; nf++) {
                    int c = wn * 32 + nf * 8 + tg * 2;
                    float2 v0, v1;
                    v0.x = tf32f(fmaxf(d[mf][nf][0], 0.f) * s0);
                    v0.y = tf32f(fmaxf(d[mf][nf][1], 0.f) * s0);
                    v1.x = tf32f(fmaxf(d[mf][nf][2], 0.f) * s1);
                    v1.y = tf32f(fmaxf(d[mf][nf][3], 0.f) * s1);
                    *(float2*)(Hs + r0 * LDH + c)       = v0;
                    *(float2*)(Hs + (r0 + 8) * LDH + c) = v1;
                }
            }
        }
        __syncthreads();
        // ---- MMA2: g2 = H @ W2 ----
        {
            float d[2][2][4];
#pragma unroll
            for (int mf = 0; mf < 2; mf++)
#pragma unroll
                for (int nf = 0; nf < 2; nf++)
#pragma unroll
                    for (int q = 0; q < 4; q++) d[mf][nf][q] = 0.f;
#pragma unroll
            for (int ks = 0; ks < 16; ks++) {
                int k0 = ks * 8;
                unsigned a[2][4];
#pragma unroll
                for (int mf = 0; mf < 2; mf++) {
                    int ar = m0 + mf * 16 + g;
                    a[mf][0] = Hsu[ar * LDH + k0 + tg];
                    a[mf][1] = Hsu[(ar + 8) * LDH + k0 + tg];
                    a[mf][2] = Hsu[ar * LDH + k0 + tg + 4];
                    a[mf][3] = Hsu[(ar + 8) * LDH + k0 + tg + 4];
                }
#pragma unroll
                for (int nf = 0; nf < 2; nf++) {
                    int bc = wn * 16 + nf * 8 + g;
                    unsigned b[2];
                    b[0] = W2u[bc * LDH + k0 + tg];
                    b[1] = W2u[bc * LDH + k0 + tg + 4];
                    mma_tf32(d[0][nf], a[0], b);
                    mma_tf32(d[1][nf], a[1], b);
                }
            }
#pragma unroll
            for (int mf = 0; mf < 2; mf++) {
                int r0 = i0 + m0 + mf * 16 + g;
#pragma unroll
                for (int nf = 0; nf < 2; nf++) {
                    int c = wn * 16 + nf * 8 + tg * 2;
                    *(float2*)(g_g2 + (size_t)r0 * F2 + c)       = make_float2(d[mf][nf][0], d[mf][nf][1]);
                    *(float2*)(g_g2 + (size_t)(r0 + 8) * F2 + c) = make_float2(d[mf][nf][2], d[mf][nf][3]);
                }
            }
        }
    }
}

// ---- SpMM layer 2 + relu + fused per-graph max readout, unroll-4 ---------
__global__ void k_spmm2(const int* __restrict__ graph_ids, float* __restrict__ out) {
    int i = blockIdx.x * 8 + (threadIdx.x >> 5);
    if (i >= N_NODES) return;
    int lane = threadIdx.x & 31;
    int beg = g_row_ptr[i], end = g_row_ptr[i + 1];
    const float2* base = (const float2*)g_g2;   // row stride 32 float2
    float2 a = make_float2(0.f, 0.f);
    int e = beg;
    for (; e + 3 < end; e += 4) {
        float2 u0 = base[(size_t)g_csr_src[e]     * 32 + lane];
        float2 u1 = base[(size_t)g_csr_src[e + 1] * 32 + lane];
        float2 u2 = base[(size_t)g_csr_src[e + 2] * 32 + lane];
        float2 u3 = base[(size_t)g_csr_src[e + 3] * 32 + lane];
        a.x += (u0.x + u1.x) + (u2.x + u3.x);
        a.y += (u0.y + u1.y) + (u2.y + u3.y);
    }
    for (; e < end; e++) {
        float2 u0 = base[(size_t)g_csr_src[e] * 32 + lane];
        a.x += u0.x;
        a.y += u0.y;
    }
    float sc = g_inv_in[i];
    float v0 = fmaxf(a.x * sc, 0.0f);
    float v1 = fmaxf(a.y * sc, 0.0f);
    int g = graph_ids[i];
    int* ob = (int*)out + g * F2;
    // non-negative floats: int compare == float compare; out pre-zeroed
    atomicMax(ob + 2 * lane,     __float_as_int(v0));
    atomicMax(ob + 2 * lane + 1, __float_as_int(v1));
}

extern "C" void kernel_launch(void* const* d_in, const int* in_sizes, int n_in,
                              void* d_out, int out_size) {
    const float* x   = (const float*)d_in[0];
    const float* W1  = (const float*)d_in[1];
    const float* W2  = (const float*)d_in[2];
    const int*   src = (const int*)d_in[3];
    const int*   dst = (const int*)d_in[4];
    const int*   gid = (const int*)d_in[5];
    float* out = (float*)d_out;

    static int smem_set = 0;
    if (!smem_set) {
        cudaFuncSetAttribute(k_gemm12, cudaFuncAttributeMaxDynamicSharedMemorySize, SM_TOTAL);
        smem_set = 1;
    }

    k_init<<<256, 256>>>(out);
    k_deg<<<(N_EDGES + 255) / 256, 256>>>(src, dst);
    k_scan_local<<<SCAN_NBLK, 1024>>>();
    k_scan_partials<<<1, 128>>>();
    k_scan_add<<<SCAN_NBLK, 1024>>>();
    k_fill<<<(N_EDGES + 255) / 256, 256>>>(src, dst);      // ncu capture slot #6
    k_spmm1<<<(N_NODES + 7) / 8, 256>>>(x);
    k_gemm12<<<148, 512, SM_TOTAL>>>(W1, W2);
    k_spmm2<<<(N_NODES + 7) / 8, 256>>>(gid, out);
}